// round 16
// baseline (speedup 1.0000x reference)
#include <cuda_runtime.h>
#include <math.h>

// BaseRoIHead multi-level RoIAlign (torchvision-style, aligned=False)
// B=2, R=512, C=256, out 7x7, sampling_ratio=2, levels p2..p6 (strides 4..64).
//
//  - PERSISTENT grid: 148*12 = 1776 CTAs of 64 threads grid-stride over the
//    7168 (roi, out-row) work items (oh innermost -> contiguous ROI range per
//    wave, preserving the R13 L2 locality win). Removes the 4.65-wave tail
//    quantization + wave-transition costs of the non-persistent launch.
//  - per item: 64 threads = 1 float4 group; border clamp folded into weights
//    (tap-b always +1 row/col, immediate addressing); y-tap rows merged at
//    setup (2/3/4-row CTA-uniform bodies)
//  - __launch_bounds__(64, 12): ~80-reg budget (R15: 56..80 regs equal-best)

#define OUT_HW 7
#define CCH 256
#define NT  64             // threads = float4 channel groups
#define NCTA_PERSIST (148 * 12)

__device__ __forceinline__ float4 f4fma(float s, float4 v, float4 a) {
    a.x = fmaf(s, v.x, a.x); a.y = fmaf(s, v.y, a.y);
    a.z = fmaf(s, v.z, a.z); a.w = fmaf(s, v.w, a.w);
    return a;
}

// NR unique y-rows; each row contributes (2 dynamic + 2 immediate) x-taps.
template <int NR>
__device__ __forceinline__ void bin_loop(
    const float* __restrict__ r0, const float* __restrict__ r1,
    const float* __restrict__ r2, const float* __restrict__ r3,
    float wy0, float wy1, float wy2, float wy3,
    const int2* __restrict__ s_xo, const float4* __restrict__ s_xw,
    float* __restrict__ orow)
{
    #pragma unroll
    for (int ow = 0; ow < OUT_HW; ow++) {
        const int2   xo = s_xo[ow];
        const float4 xw = s_xw[ow];

        const float* p00 = r0 + xo.x;
        const float* p01 = r0 + xo.y;
        const float* p10 = r1 + xo.x;
        const float* p11 = r1 + xo.y;
        const float* p20 = r2 + xo.x;
        const float* p21 = r2 + xo.y;
        const float* p30 = r3 + xo.x;
        const float* p31 = r3 + xo.y;

        float4 acc = make_float4(0.f, 0.f, 0.f, 0.f);
        {
            float4 a = *(const float4*)(p00);
            float4 bq = *(const float4*)(p00 + CCH);
            float4 c = *(const float4*)(p01);
            float4 d = *(const float4*)(p01 + CCH);
            acc = f4fma(wy0 * xw.x, a, acc);
            acc = f4fma(wy0 * xw.y, bq, acc);
            acc = f4fma(wy0 * xw.z, c, acc);
            acc = f4fma(wy0 * xw.w, d, acc);
        }
        {
            float4 a = *(const float4*)(p10);
            float4 bq = *(const float4*)(p10 + CCH);
            float4 c = *(const float4*)(p11);
            float4 d = *(const float4*)(p11 + CCH);
            acc = f4fma(wy1 * xw.x, a, acc);
            acc = f4fma(wy1 * xw.y, bq, acc);
            acc = f4fma(wy1 * xw.z, c, acc);
            acc = f4fma(wy1 * xw.w, d, acc);
        }
        if (NR > 2) {
            float4 a = *(const float4*)(p20);
            float4 bq = *(const float4*)(p20 + CCH);
            float4 c = *(const float4*)(p21);
            float4 d = *(const float4*)(p21 + CCH);
            acc = f4fma(wy2 * xw.x, a, acc);
            acc = f4fma(wy2 * xw.y, bq, acc);
            acc = f4fma(wy2 * xw.z, c, acc);
            acc = f4fma(wy2 * xw.w, d, acc);
        }
        if (NR > 3) {
            float4 a = *(const float4*)(p30);
            float4 bq = *(const float4*)(p30 + CCH);
            float4 c = *(const float4*)(p31);
            float4 d = *(const float4*)(p31 + CCH);
            acc = f4fma(wy3 * xw.x, a, acc);
            acc = f4fma(wy3 * xw.y, bq, acc);
            acc = f4fma(wy3 * xw.z, c, acc);
            acc = f4fma(wy3 * xw.w, d, acc);
        }
        *(float4*)(orow + ow * CCH) = acc;
    }
}

__global__ __launch_bounds__(NT, 12) void roialign_fpn_kernel(
    const float* __restrict__ p2, const float* __restrict__ p3,
    const float* __restrict__ p4, const float* __restrict__ p5,
    const float* __restrict__ p6, const float* __restrict__ proposals,
    float* __restrict__ out, int n_items)
{
    const int tx = threadIdx.x;          // 0..63 float4 channel group

    __shared__ int2   s_xo[OUT_HW];      // per-bin x element offsets (xa0,xa1)*CCH
    __shared__ float4 s_xw[OUT_HW];      // per-bin x weights
    __shared__ int    s_ro[4];           // merged unique row element offsets
    __shared__ float4 s_wyv;             // merged row weights * 0.25
    __shared__ int    s_nr;              // unique row count 2..4
    __shared__ const float* s_feat;

    for (int item = blockIdx.x; item < n_items; item += gridDim.x) {
        const int oh  = item % OUT_HW;   // oh innermost (locality)
        const int roi = item / OUT_HW;   // b * 512 + r
        const int b   = roi >> 9;

        if (tx < 32) {
            // uniform box/level scalars computed redundantly by every lane
            const float* box = proposals + (size_t)roi * 4;
            float bx1 = box[0], by1 = box[1], bx2 = box[2], by2 = box[3];

            float w = fmaxf(bx2 - bx1, 1.0f);
            float h = fmaxf(by2 - by1, 1.0f);
            float lvlf = floorf(4.0f + log2f(sqrtf(w * h) / 224.0f));
            int lvl = (int)fminf(fmaxf(lvlf, 2.0f), 6.0f);   // 2..6

            int H = 1024 >> lvl;
            float Hf = (float)H;
            float scale = 1.0f / (float)(1 << lvl);

            float x1s = bx1 * scale, y1s = by1 * scale;
            float bin_w = fmaxf(bx2 * scale - x1s, 1.0f) / (float)OUT_HW;
            float bin_h = fmaxf(by2 * scale - y1s, 1.0f) / (float)OUT_HW;

            if (tx < OUT_HW) {
                // lanes 0..6: both x-samples of bin `tx` (border -> weights)
                const int ow = tx;
                int   xi[2];
                float wh[2], wl[2];
                #pragma unroll
                for (int k = 0; k < 2; k++) {
                    const int j = ow * 2 + k;
                    float pos = (float)(j >> 1) + ((float)(j & 1) + 0.5f) * 0.5f;
                    float X = x1s + pos * bin_w;
                    float okf = (X >= -1.0f && X <= Hf) ? 1.0f : 0.0f;
                    float x = fminf(fmaxf(X, 0.0f), Hf - 1.0f);
                    float x0 = floorf(x);
                    int xa = (int)x0;
                    float lx = x - x0;
                    float hx = 1.0f - lx;
                    if (xa >= H - 1) {   // border: taps (H-2,H-1), weight on b
                        xa = H - 2;
                        wl[k] = okf;
                        wh[k] = 0.0f;
                    } else {
                        wh[k] = hx * okf;
                        wl[k] = lx * okf;
                    }
                    xi[k] = xa * CCH;
                }
                s_xo[ow] = make_int2(xi[0], xi[1]);
                s_xw[ow] = make_float4(wh[0], wl[0], wh[1], wl[1]);
            } else if (tx == 16) {
                // lane 16: two y-samples -> 4 row taps -> merge duplicates
                int   ro[4];
                float wv[4];
                #pragma unroll
                for (int k = 0; k < 2; k++) {
                    const int iy = oh * 2 + k;
                    float pos = (float)(iy >> 1) + ((float)(iy & 1) + 0.5f) * 0.5f;
                    float Y = y1s + pos * bin_h;
                    float okf = (Y >= -1.0f && Y <= Hf) ? 0.25f : 0.0f;
                    float y = fminf(fmaxf(Y, 0.0f), Hf - 1.0f);
                    float y0 = floorf(y);
                    int ya = (int)y0;
                    float ly = y - y0;
                    float hy = 1.0f - ly;
                    if (ya >= H - 1) {   // border: rows (H-2,H-1), weight on b
                        ya = H - 2;
                        wv[2 * k]     = 0.0f;
                        wv[2 * k + 1] = okf;
                    } else {
                        wv[2 * k]     = hy * okf;
                        wv[2 * k + 1] = ly * okf;
                    }
                    ro[2 * k]     = ya * H * CCH;
                    ro[2 * k + 1] = (ya + 1) * H * CCH;
                }
                // merge duplicate rows (outer-product: weights add)
                int   mo[4];
                float mw[4];
                int n = 0;
                #pragma unroll
                for (int t = 0; t < 4; t++) {
                    bool found = false;
                    #pragma unroll
                    for (int u = 0; u < 4; u++) {
                        if (u < n && !found && mo[u] == ro[t]) {
                            mw[u] += wv[t];
                            found = true;
                        }
                    }
                    if (!found) { mo[n] = ro[t]; mw[n] = wv[t]; n++; }
                }
                #pragma unroll
                for (int u = 0; u < 4; u++) {
                    if (u >= n) { mo[u] = mo[0]; mw[u] = 0.0f; }
                    s_ro[u] = mo[u];
                }
                s_wyv = make_float4(mw[0], mw[1], mw[2], mw[3]);
                s_nr = n;
            } else if (tx == 31) {
                const float* feats[5] = {p2, p3, p4, p5, p6};
                s_feat = feats[lvl - 2] + (size_t)b * H * H * CCH;
            }
        }
        __syncthreads();

        const int cb = tx * 4;           // channel base (float4)
        const float* base = s_feat + cb;
        const float* r0 = base + s_ro[0];
        const float* r1 = base + s_ro[1];
        const float* r2 = base + s_ro[2];
        const float* r3 = base + s_ro[3];
        const float4 wy = s_wyv;
        const int nr = s_nr;

        float* orow = out + ((size_t)roi * (OUT_HW * OUT_HW) + oh * OUT_HW) * CCH + cb;

        if (nr == 4) {
            bin_loop<4>(r0, r1, r2, r3, wy.x, wy.y, wy.z, wy.w, s_xo, s_xw, orow);
        } else if (nr == 3) {
            bin_loop<3>(r0, r1, r2, r3, wy.x, wy.y, wy.z, wy.w, s_xo, s_xw, orow);
        } else {
            bin_loop<2>(r0, r1, r2, r3, wy.x, wy.y, wy.z, wy.w, s_xo, s_xw, orow);
        }
        __syncthreads();                 // protect shared tables before rewrite
    }
}

extern "C" void kernel_launch(void* const* d_in, const int* in_sizes, int n_in,
                              void* d_out, int out_size) {
    // Identify inputs by element count (all distinct):
    // p2=33554432, p3=8388608, p4=2097152, p5=524288, p6=131072, proposals=4096
    const float* ptr[6] = {nullptr, nullptr, nullptr, nullptr, nullptr, nullptr};
    int num_rois = 1024;
    for (int i = 0; i < n_in && i < 6; i++) {
        switch (in_sizes[i]) {
            case 33554432: ptr[0] = (const float*)d_in[i]; break;  // p2
            case 8388608:  ptr[1] = (const float*)d_in[i]; break;  // p3
            case 2097152:  ptr[2] = (const float*)d_in[i]; break;  // p4
            case 524288:   ptr[3] = (const float*)d_in[i]; break;  // p5
            case 131072:   ptr[4] = (const float*)d_in[i]; break;  // p6
            default:       ptr[5] = (const float*)d_in[i];
                           num_rois = in_sizes[i] / 4;     break;  // proposals
        }
    }

    int n_items = num_rois * OUT_HW;     // 7168 (roi, out-row) work items
    int n_cta = NCTA_PERSIST;            // 148 SMs * 12 CTAs resident
    if (n_cta > n_items) n_cta = n_items;
    roialign_fpn_kernel<<<n_cta, NT>>>(ptr[0], ptr[1], ptr[2], ptr[3],
                                       ptr[4], ptr[5], (float*)d_out, n_items);
}

// round 17
// speedup vs baseline: 1.0909x; 1.0909x over previous
#include <cuda_runtime.h>
#include <math.h>

// BaseRoIHead multi-level RoIAlign (torchvision-style, aligned=False)
// B=2, R=512, C=256, out 7x7, sampling_ratio=2, levels p2..p6 (strides 4..64).
//
//  - one CTA per (roi, out-row): grid (7, 1024), oh innermost (R13 L2 locality)
//    [R16 showed the persistent-grid variant regresses: per-item barriers
//     serialize setup/compute across items -> reverted]
//  - 64 threads = 1 float4 group; border clamp folded into weights so tap-b is
//    always +1 row/col (immediate addressing)
//  - y-tap rows merged at setup (separable outer product); CTA-uniform switch
//    picks 2/3/4-row body (R14 win)
//  - __launch_bounds__(64, 12): ~80-reg budget (R15 frontier 56..80 flat-best)
//  - NEW: output stores use st.global.cs (evict-first streaming) so the 51MB
//    never-re-read output stream does not evict the ~44MB feature working set
//    from L2 -> more gathers hit L2 (234cyc) instead of DRAM (577cyc)

#define OUT_HW 7
#define CCH 256
#define NT  64             // threads = float4 channel groups

__device__ __forceinline__ float4 f4fma(float s, float4 v, float4 a) {
    a.x = fmaf(s, v.x, a.x); a.y = fmaf(s, v.y, a.y);
    a.z = fmaf(s, v.z, a.z); a.w = fmaf(s, v.w, a.w);
    return a;
}

__device__ __forceinline__ void stcs4(float* p, float4 v) {
    asm volatile("st.global.cs.v4.f32 [%0], {%1, %2, %3, %4};"
                 :: "l"(p), "f"(v.x), "f"(v.y), "f"(v.z), "f"(v.w)
                 : "memory");
}

// NR unique y-rows; each row contributes (2 dynamic + 2 immediate) x-taps.
template <int NR>
__device__ __forceinline__ void bin_loop(
    const float* __restrict__ r0, const float* __restrict__ r1,
    const float* __restrict__ r2, const float* __restrict__ r3,
    float wy0, float wy1, float wy2, float wy3,
    const int2* __restrict__ s_xo, const float4* __restrict__ s_xw,
    float* __restrict__ orow)
{
    #pragma unroll
    for (int ow = 0; ow < OUT_HW; ow++) {
        const int2   xo = s_xo[ow];
        const float4 xw = s_xw[ow];

        const float* p00 = r0 + xo.x;
        const float* p01 = r0 + xo.y;
        const float* p10 = r1 + xo.x;
        const float* p11 = r1 + xo.y;
        const float* p20 = r2 + xo.x;
        const float* p21 = r2 + xo.y;
        const float* p30 = r3 + xo.x;
        const float* p31 = r3 + xo.y;

        float4 acc = make_float4(0.f, 0.f, 0.f, 0.f);
        {
            float4 a = *(const float4*)(p00);
            float4 bq = *(const float4*)(p00 + CCH);
            float4 c = *(const float4*)(p01);
            float4 d = *(const float4*)(p01 + CCH);
            acc = f4fma(wy0 * xw.x, a, acc);
            acc = f4fma(wy0 * xw.y, bq, acc);
            acc = f4fma(wy0 * xw.z, c, acc);
            acc = f4fma(wy0 * xw.w, d, acc);
        }
        {
            float4 a = *(const float4*)(p10);
            float4 bq = *(const float4*)(p10 + CCH);
            float4 c = *(const float4*)(p11);
            float4 d = *(const float4*)(p11 + CCH);
            acc = f4fma(wy1 * xw.x, a, acc);
            acc = f4fma(wy1 * xw.y, bq, acc);
            acc = f4fma(wy1 * xw.z, c, acc);
            acc = f4fma(wy1 * xw.w, d, acc);
        }
        if (NR > 2) {
            float4 a = *(const float4*)(p20);
            float4 bq = *(const float4*)(p20 + CCH);
            float4 c = *(const float4*)(p21);
            float4 d = *(const float4*)(p21 + CCH);
            acc = f4fma(wy2 * xw.x, a, acc);
            acc = f4fma(wy2 * xw.y, bq, acc);
            acc = f4fma(wy2 * xw.z, c, acc);
            acc = f4fma(wy2 * xw.w, d, acc);
        }
        if (NR > 3) {
            float4 a = *(const float4*)(p30);
            float4 bq = *(const float4*)(p30 + CCH);
            float4 c = *(const float4*)(p31);
            float4 d = *(const float4*)(p31 + CCH);
            acc = f4fma(wy3 * xw.x, a, acc);
            acc = f4fma(wy3 * xw.y, bq, acc);
            acc = f4fma(wy3 * xw.z, c, acc);
            acc = f4fma(wy3 * xw.w, d, acc);
        }
        stcs4(orow + ow * CCH, acc);
    }
}

__global__ __launch_bounds__(NT, 12) void roialign_fpn_kernel(
    const float* __restrict__ p2, const float* __restrict__ p3,
    const float* __restrict__ p4, const float* __restrict__ p5,
    const float* __restrict__ p6, const float* __restrict__ proposals,
    float* __restrict__ out)
{
    const int oh  = blockIdx.x;          // output row 0..6 (innermost)
    const int roi = blockIdx.y;          // b * 512 + r
    const int b   = roi >> 9;
    const int tx  = threadIdx.x;         // 0..63 float4 channel group

    __shared__ int2   s_xo[OUT_HW];      // per-bin x element offsets (xa0,xa1)*CCH
    __shared__ float4 s_xw[OUT_HW];      // per-bin x weights
    __shared__ int    s_ro[4];           // merged unique row element offsets
    __shared__ float4 s_wyv;             // merged row weights * 0.25
    __shared__ int    s_nr;              // unique row count 2..4
    __shared__ const float* s_feat;

    if (tx < 32) {
        // uniform box/level scalars computed redundantly by every lane
        const float* box = proposals + (size_t)roi * 4;
        float bx1 = box[0], by1 = box[1], bx2 = box[2], by2 = box[3];

        float w = fmaxf(bx2 - bx1, 1.0f);
        float h = fmaxf(by2 - by1, 1.0f);
        float lvlf = floorf(4.0f + log2f(sqrtf(w * h) / 224.0f));
        int lvl = (int)fminf(fmaxf(lvlf, 2.0f), 6.0f);   // 2..6

        int H = 1024 >> lvl;
        float Hf = (float)H;
        float scale = 1.0f / (float)(1 << lvl);

        float x1s = bx1 * scale, y1s = by1 * scale;
        float bin_w = fmaxf(bx2 * scale - x1s, 1.0f) / (float)OUT_HW;
        float bin_h = fmaxf(by2 * scale - y1s, 1.0f) / (float)OUT_HW;

        if (tx < OUT_HW) {
            // lanes 0..6: both x-samples of bin `tx` (border folded to weights)
            const int ow = tx;
            int   xi[2];
            float wh[2], wl[2];
            #pragma unroll
            for (int k = 0; k < 2; k++) {
                const int j = ow * 2 + k;
                float pos = (float)(j >> 1) + ((float)(j & 1) + 0.5f) * 0.5f;
                float X = x1s + pos * bin_w;
                float okf = (X >= -1.0f && X <= Hf) ? 1.0f : 0.0f;
                float x = fminf(fmaxf(X, 0.0f), Hf - 1.0f);
                float x0 = floorf(x);
                int xa = (int)x0;
                float lx = x - x0;
                float hx = 1.0f - lx;
                if (xa >= H - 1) {       // border: taps (H-2, H-1), weight on b
                    xa = H - 2;
                    wl[k] = okf;
                    wh[k] = 0.0f;
                } else {
                    wh[k] = hx * okf;
                    wl[k] = lx * okf;
                }
                xi[k] = xa * CCH;
            }
            s_xo[ow] = make_int2(xi[0], xi[1]);
            s_xw[ow] = make_float4(wh[0], wl[0], wh[1], wl[1]);
        } else if (tx == 16) {
            // lane 16: two y-samples -> 4 (row, weight) taps -> merge duplicates
            int   ro[4];
            float wv[4];
            #pragma unroll
            for (int k = 0; k < 2; k++) {
                const int iy = oh * 2 + k;
                float pos = (float)(iy >> 1) + ((float)(iy & 1) + 0.5f) * 0.5f;
                float Y = y1s + pos * bin_h;
                float okf = (Y >= -1.0f && Y <= Hf) ? 0.25f : 0.0f;
                float y = fminf(fmaxf(Y, 0.0f), Hf - 1.0f);
                float y0 = floorf(y);
                int ya = (int)y0;
                float ly = y - y0;
                float hy = 1.0f - ly;
                if (ya >= H - 1) {       // border: rows (H-2, H-1), weight on b
                    ya = H - 2;
                    wv[2 * k]     = 0.0f;
                    wv[2 * k + 1] = okf;
                } else {
                    wv[2 * k]     = hy * okf;
                    wv[2 * k + 1] = ly * okf;
                }
                ro[2 * k]     = ya * H * CCH;
                ro[2 * k + 1] = (ya + 1) * H * CCH;
            }
            // merge duplicate rows (outer-product separability: weights add)
            int   mo[4];
            float mw[4];
            int n = 0;
            #pragma unroll
            for (int t = 0; t < 4; t++) {
                bool found = false;
                #pragma unroll
                for (int u = 0; u < 4; u++) {
                    if (u < n && !found && mo[u] == ro[t]) {
                        mw[u] += wv[t];
                        found = true;
                    }
                }
                if (!found) { mo[n] = ro[t]; mw[n] = wv[t]; n++; }
            }
            #pragma unroll
            for (int u = 0; u < 4; u++) {
                if (u >= n) { mo[u] = mo[0]; mw[u] = 0.0f; }
                s_ro[u] = mo[u];
            }
            s_wyv = make_float4(mw[0], mw[1], mw[2], mw[3]);
            s_nr = n;
        } else if (tx == 31) {
            const float* feats[5] = {p2, p3, p4, p5, p6};
            s_feat = feats[lvl - 2] + (size_t)b * H * H * CCH;
        }
    }
    __syncthreads();

    const int cb = tx * 4;               // channel base (float4)
    const float* base = s_feat + cb;
    const float* r0 = base + s_ro[0];
    const float* r1 = base + s_ro[1];
    const float* r2 = base + s_ro[2];
    const float* r3 = base + s_ro[3];
    const float4 wy = s_wyv;
    const int nr = s_nr;

    float* orow = out + ((size_t)roi * (OUT_HW * OUT_HW) + oh * OUT_HW) * CCH + cb;

    if (nr == 4) {
        bin_loop<4>(r0, r1, r2, r3, wy.x, wy.y, wy.z, wy.w, s_xo, s_xw, orow);
    } else if (nr == 3) {
        bin_loop<3>(r0, r1, r2, r3, wy.x, wy.y, wy.z, wy.w, s_xo, s_xw, orow);
    } else {
        bin_loop<2>(r0, r1, r2, r3, wy.x, wy.y, wy.z, wy.w, s_xo, s_xw, orow);
    }
}

extern "C" void kernel_launch(void* const* d_in, const int* in_sizes, int n_in,
                              void* d_out, int out_size) {
    // Identify inputs by element count (all distinct):
    // p2=33554432, p3=8388608, p4=2097152, p5=524288, p6=131072, proposals=4096
    const float* ptr[6] = {nullptr, nullptr, nullptr, nullptr, nullptr, nullptr};
    int num_rois = 1024;
    for (int i = 0; i < n_in && i < 6; i++) {
        switch (in_sizes[i]) {
            case 33554432: ptr[0] = (const float*)d_in[i]; break;  // p2
            case 8388608:  ptr[1] = (const float*)d_in[i]; break;  // p3
            case 2097152:  ptr[2] = (const float*)d_in[i]; break;  // p4
            case 524288:   ptr[3] = (const float*)d_in[i]; break;  // p5
            case 131072:   ptr[4] = (const float*)d_in[i]; break;  // p6
            default:       ptr[5] = (const float*)d_in[i];
                           num_rois = in_sizes[i] / 4;     break;  // proposals
        }
    }

    dim3 grid(OUT_HW, num_rois, 1);      // oh innermost: ROI's 7 CTAs adjacent
    roialign_fpn_kernel<<<grid, NT>>>(ptr[0], ptr[1], ptr[2], ptr[3],
                                      ptr[4], ptr[5], (float*)d_out);
}